// round 1
// baseline (speedup 1.0000x reference)
#include <cuda_runtime.h>
#include <cstdint>

#define T_SEQ   512
#define B_DIM   256
#define H_DIM   256
#define E_DIM   6
#define C_DIM   10
#define CLUSTER 8
#define G_COLS  16          // batch columns per cluster
#define NTHREADS 256

// Dynamic smem layout (floats):
//  hbuf : [2][256][16]   = 8192   (ping-pong full-h replica, col-contiguous)
//  part : [2][128][20]   = 5120   (K-half partials, padded stride 20 for bank-free STS.128)
//  wxs  : [4][32][6]     = 768    (this CTA's Wx rows)
//  xes  : [6][16]        = 96     (x_t embeddings for this cluster's columns)
//  bsh  : [4][16]        = 64     (bias per COLUMN — faithful (H,B)+(H,) broadcast, H==B)
#define OFF_HBUF 0
#define OFF_PART 8192
#define OFF_WX   13312
#define OFF_XE   14080
#define OFF_B    14176
#define SMEM_FLOATS 14240
#define SMEM_BYTES (SMEM_FLOATS * 4)

__device__ __forceinline__ uint32_t smem_u32(const void* p) {
    return (uint32_t)__cvta_generic_to_shared(p);
}
__device__ __forceinline__ uint32_t mapa_rank(uint32_t addr, int r) {
    uint32_t ret;
    asm("mapa.shared::cluster.u32 %0, %1, %2;" : "=r"(ret) : "r"(addr), "r"(r));
    return ret;
}
__device__ __forceinline__ void st_cluster_f32(uint32_t addr, float v) {
    asm volatile("st.shared::cluster.f32 [%0], %1;" :: "r"(addr), "f"(v) : "memory");
}
__device__ __forceinline__ void cluster_sync_() {
    asm volatile("barrier.cluster.arrive.aligned;\n\tbarrier.cluster.wait.aligned;" ::: "memory");
}
__device__ __forceinline__ float sigf(float x)  { return 1.0f / (1.0f + __expf(-x)); }
__device__ __forceinline__ float tanhf_(float x){ return 2.0f / (1.0f + __expf(-2.0f * x)) - 1.0f; }

extern "C" __global__ void __launch_bounds__(NTHREADS, 1) __cluster_dims__(CLUSTER, 1, 1)
lstm_cluster_kernel(const int* __restrict__ x, const float* __restrict__ emb,
                    const float* __restrict__ Wxg, const float* __restrict__ Whg, const float* __restrict__ bg,
                    const float* __restrict__ Wxi, const float* __restrict__ Whi, const float* __restrict__ bi,
                    const float* __restrict__ Wxf, const float* __restrict__ Whf, const float* __restrict__ bf,
                    const float* __restrict__ Wxo, const float* __restrict__ Who, const float* __restrict__ bo,
                    const float* __restrict__ Wp,  const float* __restrict__ bp,
                    float* __restrict__ out)
{
    extern __shared__ float sm[];
    float* hbuf = sm + OFF_HBUF;
    float* part = sm + OFF_PART;
    float* wxs  = sm + OFF_WX;
    float* xes  = sm + OFF_XE;
    float* bsh  = sm + OFF_B;

    const int tid  = threadIdx.x;
    const int rank = blockIdx.x & (CLUSTER - 1);
    const int cid  = blockIdx.x / CLUSTER;
    const int col0 = cid * G_COLS;

    const int row_local = tid & 127;    // gate-row within CTA (0..127)
    const int khalf     = tid >> 7;     // 0/1 : which half of K this thread accumulates
    const int gate      = row_local >> 5;
    const int jrow      = row_local & 31;
    const int hrow      = rank * 32 + jrow;   // global hidden index of this gate-row

    const float* WhTab[4] = { Whg, Whi, Whf, Who };
    const float* WxTab[4] = { Wxg, Wxi, Wxf, Wxo };
    const float* bTab[4]  = { bg,  bi,  bf,  bo  };

    // ---- register-resident recurrent weights: 128 fp32 per thread ----
    float wreg[128];
    {
        const float* wrow = WhTab[gate] + hrow * H_DIM + khalf * 128;
        #pragma unroll
        for (int k = 0; k < 128; k++) wreg[k] = wrow[k];
    }

    // ---- smem init ----
    for (int i = tid; i < H_DIM * G_COLS; i += NTHREADS) hbuf[i] = 0.0f;   // h0 = 0 (buffer 0)
    for (int i = tid; i < 4 * 32 * E_DIM; i += NTHREADS) {
        int q = i / (32 * E_DIM);
        int r = i % (32 * E_DIM);
        int j = r / E_DIM, e = r % E_DIM;
        wxs[i] = WxTab[q][(rank * 32 + j) * E_DIM + e];
    }
    if (tid < 64) {                      // bias broadcasts over the trailing BATCH axis
        int q = tid >> 4, c = tid & 15;
        bsh[tid] = bTab[q][col0 + c];
    }
    __syncthreads();

    // Precompute peer hbuf base addresses (mapa once, reuse with offsets)
    uint32_t mybase = smem_u32(hbuf);
    uint32_t peer[CLUSTER];
    #pragma unroll
    for (int r = 0; r < CLUSTER; r++) peer[r] = mapa_rank(mybase, r);

    cluster_sync_();

    // finalize mapping: thread handles (fj, fcol) and (fj+16, fcol)
    const int fcol = tid & 15;
    const int fj   = tid >> 4;           // 0..15
    float cst1 = 0.0f, cst2 = 0.0f;      // cell state, register-resident

    int p = 0;
    for (int t = 0; t < T_SEQ; t++) {
        // x_t embedding for this cluster's 16 columns
        if (tid < G_COLS) {
            int xi = x[(col0 + tid) * T_SEQ + t];
            const float* er = emb + xi * E_DIM;
            #pragma unroll
            for (int e = 0; e < E_DIM; e++) xes[e * G_COLS + tid] = er[e];
        }

        // ---- partial mat-vec: 128 k-iters x 16 columns, weights in regs ----
        float acc[16];
        #pragma unroll
        for (int c = 0; c < 16; c++) acc[c] = 0.0f;
        const float4* hb4 = (const float4*)(hbuf + p * (H_DIM * G_COLS) + khalf * 128 * G_COLS);
        #pragma unroll
        for (int k = 0; k < 128; k++) {
            const float  w  = wreg[k];
            const float4 h0 = hb4[k * 4 + 0];
            const float4 h1 = hb4[k * 4 + 1];
            const float4 h2 = hb4[k * 4 + 2];
            const float4 h3 = hb4[k * 4 + 3];
            acc[ 0] = fmaf(w, h0.x, acc[ 0]);  acc[ 1] = fmaf(w, h0.y, acc[ 1]);
            acc[ 2] = fmaf(w, h0.z, acc[ 2]);  acc[ 3] = fmaf(w, h0.w, acc[ 3]);
            acc[ 4] = fmaf(w, h1.x, acc[ 4]);  acc[ 5] = fmaf(w, h1.y, acc[ 5]);
            acc[ 6] = fmaf(w, h1.z, acc[ 6]);  acc[ 7] = fmaf(w, h1.w, acc[ 7]);
            acc[ 8] = fmaf(w, h2.x, acc[ 8]);  acc[ 9] = fmaf(w, h2.y, acc[ 9]);
            acc[10] = fmaf(w, h2.z, acc[10]);  acc[11] = fmaf(w, h2.w, acc[11]);
            acc[12] = fmaf(w, h3.x, acc[12]);  acc[13] = fmaf(w, h3.y, acc[13]);
            acc[14] = fmaf(w, h3.z, acc[14]);  acc[15] = fmaf(w, h3.w, acc[15]);
        }
        // store partials (stride 20 floats -> conflict-free STS.128)
        {
            float* pr = part + (khalf * 128 + row_local) * 20;
            ((float4*)pr)[0] = make_float4(acc[ 0], acc[ 1], acc[ 2], acc[ 3]);
            ((float4*)pr)[1] = make_float4(acc[ 4], acc[ 5], acc[ 6], acc[ 7]);
            ((float4*)pr)[2] = make_float4(acc[ 8], acc[ 9], acc[10], acc[11]);
            ((float4*)pr)[3] = make_float4(acc[12], acc[13], acc[14], acc[15]);
        }
        __syncthreads();

        // ---- finalize: combine halves + Wx*x + bias, gates, c/h update ----
        float hn1, hn2;
        #pragma unroll
        for (int item = 0; item < 2; item++) {
            const int j = fj + item * 16;     // local hidden index 0..31
            float pre[4];
            #pragma unroll
            for (int q = 0; q < 4; q++) {
                const int rl = q * 32 + j;
                float s = part[rl * 20 + fcol] + part[(128 + rl) * 20 + fcol] + bsh[q * 16 + fcol];
                #pragma unroll
                for (int e = 0; e < E_DIM; e++)
                    s = fmaf(wxs[rl * E_DIM + e], xes[e * 16 + fcol], s);
                pre[q] = s;
            }
            float g  = tanhf_(pre[0]);
            float ig = sigf(pre[1]);
            float fg = sigf(pre[2]);
            float og = sigf(pre[3]);
            float& cs = item ? cst2 : cst1;
            cs = fmaf(g, ig, cs * fg);
            float hn = tanhf_(cs) * og;
            if (item) hn2 = hn; else hn1 = hn;
        }

        // ---- broadcast h chunk to all 8 CTAs' hbuf[p^1] ----
        const uint32_t off1 = (uint32_t)(((p ^ 1) * (H_DIM * G_COLS) + (rank * 32 + fj) * G_COLS + fcol) * 4);
        const uint32_t off2 = off1 + 16u * G_COLS * 4u;
        #pragma unroll
        for (int r = 0; r < CLUSTER; r++) {
            st_cluster_f32(peer[r] + off1, hn1);
            st_cluster_f32(peer[r] + off2, hn2);
        }
        cluster_sync_();
        p ^= 1;
    }

    // ---- projection: out[b, c] = sum_k Wp[c,k] h[k,b] + bp[c] ----
    if (rank == 0 && tid < G_COLS * C_DIM) {
        const int col = tid / C_DIM;
        const int cls = tid % C_DIM;
        const float* wpr = Wp + cls * H_DIM;
        const float* hfin = hbuf + p * (H_DIM * G_COLS);
        float s = bp[cls];
        #pragma unroll 8
        for (int k = 0; k < H_DIM; k++)
            s = fmaf(wpr[k], hfin[k * G_COLS + col], s);
        out[(col0 + col) * C_DIM + cls] = s;
    }
}

extern "C" void kernel_launch(void* const* d_in, const int* in_sizes, int n_in,
                              void* d_out, int out_size) {
    (void)in_sizes; (void)n_in; (void)out_size;
    const int*   x   = (const int*)  d_in[0];
    const float* emb = (const float*)d_in[1];
    const float* Wxg = (const float*)d_in[2];
    const float* Whg = (const float*)d_in[3];
    const float* bg  = (const float*)d_in[4];
    const float* Wxi = (const float*)d_in[5];
    const float* Whi = (const float*)d_in[6];
    const float* bi  = (const float*)d_in[7];
    const float* Wxf = (const float*)d_in[8];
    const float* Whf = (const float*)d_in[9];
    const float* bf  = (const float*)d_in[10];
    const float* Wxo = (const float*)d_in[11];
    const float* Who = (const float*)d_in[12];
    const float* bo  = (const float*)d_in[13];
    const float* Wp  = (const float*)d_in[14];
    const float* bp  = (const float*)d_in[15];
    float* out = (float*)d_out;

    cudaFuncSetAttribute(lstm_cluster_kernel,
                         cudaFuncAttributeMaxDynamicSharedMemorySize, SMEM_BYTES);
    // 16 clusters of 8 CTAs = 128 CTAs (single wave on 148 SMs)
    lstm_cluster_kernel<<<(B_DIM / G_COLS) * CLUSTER, NTHREADS, SMEM_BYTES>>>(
        x, emb, Wxg, Whg, bg, Wxi, Whi, bi, Wxf, Whf, bf, Wxo, Who, bo, Wp, bp, out);
}

// round 2
// speedup vs baseline: 2.2474x; 2.2474x over previous
#include <cuda_runtime.h>
#include <cstdint>

#define T_SEQ   512
#define B_DIM   256
#define H_DIM   256
#define E_DIM   6
#define C_DIM   10
#define CLUSTER 8
#define G_COLS  16          // batch columns per cluster
#define NTHREADS 256

// Dynamic smem layout (floats):
//  hbuf : [2][256][16]      = 8192   (ping-pong full-h replica, col-contiguous)
//  part : [4][128][20]      = 10240  (k-split partials, pad 20 for conflict-free STS.128)
//  wxs  : [4][32][6]        = 768
//  xes  : [6][16]           = 96
//  bsh  : [4][16]           = 64     (bias per COLUMN — faithful (H,B)+(H,) broadcast, H==B)
#define OFF_HBUF 0
#define OFF_PART 8192
#define OFF_WX   18432
#define OFF_XE   19200
#define OFF_B    19296
#define SMEM_FLOATS 19360
#define SMEM_BYTES (SMEM_FLOATS * 4)

__device__ __forceinline__ uint32_t smem_u32(const void* p) {
    return (uint32_t)__cvta_generic_to_shared(p);
}
__device__ __forceinline__ uint32_t mapa_rank(uint32_t addr, int r) {
    uint32_t ret;
    asm("mapa.shared::cluster.u32 %0, %1, %2;" : "=r"(ret) : "r"(addr), "r"(r));
    return ret;
}
__device__ __forceinline__ void st_cluster_u64(uint32_t addr, uint64_t v) {
    asm volatile("st.shared::cluster.u64 [%0], %1;" :: "r"(addr), "l"(v) : "memory");
}
__device__ __forceinline__ void cluster_sync_() {
    asm volatile("barrier.cluster.arrive.aligned;\n\tbarrier.cluster.wait.aligned;" ::: "memory");
}
// ---- packed f32x2 helpers ----
__device__ __forceinline__ uint64_t pk2(float w) {
    uint64_t r; uint32_t u = __float_as_uint(w);
    asm("mov.b64 %0, {%1, %1};" : "=l"(r) : "r"(u));
    return r;
}
__device__ __forceinline__ uint64_t pk2ab(float a, float b) {
    uint64_t r; uint32_t ua = __float_as_uint(a), ub = __float_as_uint(b);
    asm("mov.b64 %0, {%1, %2};" : "=l"(r) : "r"(ua), "r"(ub));
    return r;
}
__device__ __forceinline__ float2 unpk2(uint64_t v) {
    uint32_t lo, hi;
    asm("mov.b64 {%0, %1}, %2;" : "=r"(lo), "=r"(hi) : "l"(v));
    return make_float2(__uint_as_float(lo), __uint_as_float(hi));
}
__device__ __forceinline__ uint64_t fma2(uint64_t a, uint64_t b, uint64_t c) {
    uint64_t d;
    asm("fma.rn.f32x2 %0, %1, %2, %3;" : "=l"(d) : "l"(a), "l"(b), "l"(c));
    return d;
}
__device__ __forceinline__ uint64_t add2(uint64_t a, uint64_t b) {
    uint64_t d;
    asm("add.rn.f32x2 %0, %1, %2;" : "=l"(d) : "l"(a), "l"(b));
    return d;
}
__device__ __forceinline__ float sigf(float x)  { return 1.0f / (1.0f + __expf(-x)); }
__device__ __forceinline__ float tanhf_(float x){ return 2.0f / (1.0f + __expf(-2.0f * x)) - 1.0f; }

extern "C" __global__ void __launch_bounds__(NTHREADS, 1) __cluster_dims__(CLUSTER, 1, 1)
lstm_cluster_kernel(const int* __restrict__ x, const float* __restrict__ emb,
                    const float* __restrict__ Wxg, const float* __restrict__ Whg, const float* __restrict__ bg,
                    const float* __restrict__ Wxi, const float* __restrict__ Whi, const float* __restrict__ bi,
                    const float* __restrict__ Wxf, const float* __restrict__ Whf, const float* __restrict__ bf,
                    const float* __restrict__ Wxo, const float* __restrict__ Who, const float* __restrict__ bo,
                    const float* __restrict__ Wp,  const float* __restrict__ bp,
                    float* __restrict__ out)
{
    extern __shared__ float sm[];
    float* hbuf = sm + OFF_HBUF;
    float* part = sm + OFF_PART;
    float* wxs  = sm + OFF_WX;
    float* xes  = sm + OFF_XE;
    float* bsh  = sm + OFF_B;

    const int tid  = threadIdx.x;
    const int rank = blockIdx.x & (CLUSTER - 1);
    const int cid  = blockIdx.x / CLUSTER;
    const int col0 = cid * G_COLS;

    // Partial-phase decomposition: 256 thr = 32 rows x 2 gate-pairs x 4 k-splits
    const int jrow = tid & 31;            // hidden row within this CTA's 32
    const int gp   = (tid >> 5) & 1;      // gate pair: {g,i} or {f,o}
    const int ks   = tid >> 6;            // k-split 0..3 (64 k each)
    const int hrow = rank * 32 + jrow;    // global hidden row

    const float* WhTab[4] = { Whg, Whi, Whf, Who };
    const float* WxTab[4] = { Wxg, Wxi, Wxf, Wxo };
    const float* bTab[4]  = { bg,  bi,  bf,  bo  };

    // ---- register-resident recurrent weights: 2 gates x 64 k = 128 fp32 ----
    float wreg[2][64];
    #pragma unroll
    for (int g = 0; g < 2; g++) {
        const float* wrow = WhTab[2 * gp + g] + hrow * H_DIM + ks * 64;
        #pragma unroll
        for (int k = 0; k < 64; k++) wreg[g][k] = wrow[k];
    }

    // ---- smem init ----
    for (int i = tid; i < H_DIM * G_COLS; i += NTHREADS) hbuf[i] = 0.0f;   // h0 = 0
    for (int i = tid; i < 4 * 32 * E_DIM; i += NTHREADS) {
        int q = i / (32 * E_DIM);
        int r = i % (32 * E_DIM);
        int j = r / E_DIM, e = r % E_DIM;
        wxs[i] = WxTab[q][(rank * 32 + j) * E_DIM + e];
    }
    if (tid < 64) {                      // bias broadcasts over trailing BATCH axis
        int q = tid >> 4, c = tid & 15;
        bsh[tid] = bTab[q][col0 + c];
    }
    __syncthreads();

    uint32_t mybase = smem_u32(hbuf);
    uint32_t peer[CLUSTER];
    #pragma unroll
    for (int r = 0; r < CLUSTER; r++) peer[r] = mapa_rank(mybase, r);

    cluster_sync_();

    // Finalize mapping: thread -> (row fj, column pair 2*fcp, 2*fcp+1)
    const int fj  = tid >> 3;            // 0..31
    const int fcp = tid & 7;             // 0..7
    float cstA = 0.0f, cstB = 0.0f;      // cell states for the two columns

    int p = 0;
    for (int t = 0; t < T_SEQ; t++) {
        if (tid < G_COLS) {
            int xi = x[(col0 + tid) * T_SEQ + t];
            const float* er = emb + xi * E_DIM;
            #pragma unroll
            for (int e = 0; e < E_DIM; e++) xes[e * G_COLS + tid] = er[e];
        }

        // ---- partial mat-vec: 64 k-iters, 2 gates, 16 cols as 8 f32x2 ----
        uint64_t acc[2][8];
        #pragma unroll
        for (int g = 0; g < 2; g++)
            #pragma unroll
            for (int c = 0; c < 8; c++) acc[g][c] = 0ull;

        const ulonglong2* hb2 =
            (const ulonglong2*)(hbuf + p * (H_DIM * G_COLS)) + (size_t)ks * 64 * 4;
        #pragma unroll
        for (int k = 0; k < 64; k++) {
            const ulonglong2 v0 = hb2[k * 4 + 0];
            const ulonglong2 v1 = hb2[k * 4 + 1];
            const ulonglong2 v2 = hb2[k * 4 + 2];
            const ulonglong2 v3 = hb2[k * 4 + 3];
            #pragma unroll
            for (int g = 0; g < 2; g++) {
                const uint64_t wp = pk2(wreg[g][k]);
                acc[g][0] = fma2(wp, v0.x, acc[g][0]);
                acc[g][1] = fma2(wp, v0.y, acc[g][1]);
                acc[g][2] = fma2(wp, v1.x, acc[g][2]);
                acc[g][3] = fma2(wp, v1.y, acc[g][3]);
                acc[g][4] = fma2(wp, v2.x, acc[g][4]);
                acc[g][5] = fma2(wp, v2.y, acc[g][5]);
                acc[g][6] = fma2(wp, v3.x, acc[g][6]);
                acc[g][7] = fma2(wp, v3.y, acc[g][7]);
            }
        }
        // store partials: part[ks][gate*32+jrow][col], stride 20 -> conflict-free
        #pragma unroll
        for (int g = 0; g < 2; g++) {
            float* pr = part + (ks * 128 + (2 * gp + g) * 32 + jrow) * 20;
            ((ulonglong2*)pr)[0] = make_ulonglong2(acc[g][0], acc[g][1]);
            ((ulonglong2*)pr)[1] = make_ulonglong2(acc[g][2], acc[g][3]);
            ((ulonglong2*)pr)[2] = make_ulonglong2(acc[g][4], acc[g][5]);
            ((ulonglong2*)pr)[3] = make_ulonglong2(acc[g][6], acc[g][7]);
        }
        __syncthreads();

        // ---- finalize: sum 4 k-splits + Wx*x + bias, gates, c/h update ----
        uint64_t xe2[E_DIM];
        #pragma unroll
        for (int e = 0; e < E_DIM; e++)
            xe2[e] = *(const uint64_t*)&xes[e * 16 + 2 * fcp];

        float preA[4], preB[4];
        #pragma unroll
        for (int q = 0; q < 4; q++) {
            const int rl = q * 32 + fj;
            uint64_t s2 = *(const uint64_t*)&bsh[q * 16 + 2 * fcp];
            #pragma unroll
            for (int kss = 0; kss < 4; kss++)
                s2 = add2(s2, *(const uint64_t*)&part[(kss * 128 + rl) * 20 + 2 * fcp]);
            #pragma unroll
            for (int e = 0; e < E_DIM; e++)
                s2 = fma2(pk2(wxs[rl * E_DIM + e]), xe2[e], s2);
            float2 sv = unpk2(s2);
            preA[q] = sv.x; preB[q] = sv.y;
        }

        float gA = tanhf_(preA[0]), iA = sigf(preA[1]), fA = sigf(preA[2]), oA = sigf(preA[3]);
        float gB = tanhf_(preB[0]), iB = sigf(preB[1]), fB = sigf(preB[2]), oB = sigf(preB[3]);
        cstA = fmaf(gA, iA, cstA * fA);
        cstB = fmaf(gB, iB, cstB * fB);
        const float hnA = tanhf_(cstA) * oA;
        const float hnB = tanhf_(cstB) * oB;
        const uint64_t hn2 = pk2ab(hnA, hnB);

        // ---- broadcast h column-pair to all 8 CTAs' hbuf[p^1] ----
        const uint32_t off = (uint32_t)((((p ^ 1) * (H_DIM * G_COLS)) +
                                        (rank * 32 + fj) * G_COLS + 2 * fcp) * 4);
        #pragma unroll
        for (int r = 0; r < CLUSTER; r++)
            st_cluster_u64(peer[r] + off, hn2);

        cluster_sync_();
        p ^= 1;
    }

    // ---- projection: out[b, c] = sum_k Wp[c,k] h[k,b] + bp[c] ----
    if (rank == 0 && tid < G_COLS * C_DIM) {
        const int col = tid / C_DIM;
        const int cls = tid % C_DIM;
        const float* wpr = Wp + cls * H_DIM;
        const float* hfin = hbuf + p * (H_DIM * G_COLS);
        float s = bp[cls];
        #pragma unroll 8
        for (int k = 0; k < H_DIM; k++)
            s = fmaf(wpr[k], hfin[k * G_COLS + col], s);
        out[(col0 + col) * C_DIM + cls] = s;
    }
}

extern "C" void kernel_launch(void* const* d_in, const int* in_sizes, int n_in,
                              void* d_out, int out_size) {
    (void)in_sizes; (void)n_in; (void)out_size;
    const int*   x   = (const int*)  d_in[0];
    const float* emb = (const float*)d_in[1];
    const float* Wxg = (const float*)d_in[2];
    const float* Whg = (const float*)d_in[3];
    const float* bg  = (const float*)d_in[4];
    const float* Wxi = (const float*)d_in[5];
    const float* Whi = (const float*)d_in[6];
    const float* bi  = (const float*)d_in[7];
    const float* Wxf = (const float*)d_in[8];
    const float* Whf = (const float*)d_in[9];
    const float* bf  = (const float*)d_in[10];
    const float* Wxo = (const float*)d_in[11];
    const float* Who = (const float*)d_in[12];
    const float* bo  = (const float*)d_in[13];
    const float* Wp  = (const float*)d_in[14];
    const float* bp  = (const float*)d_in[15];
    float* out = (float*)d_out;

    cudaFuncSetAttribute(lstm_cluster_kernel,
                         cudaFuncAttributeMaxDynamicSharedMemorySize, SMEM_BYTES);
    lstm_cluster_kernel<<<(B_DIM / G_COLS) * CLUSTER, NTHREADS, SMEM_BYTES>>>(
        x, emb, Wxg, Whg, bg, Wxi, Whi, bi, Wxf, Whf, bf, Wxo, Who, bo, Wp, bp, out);
}